// round 17
// baseline (speedup 1.0000x reference)
#include <cuda_runtime.h>

// MaskedNorm: X[B,N,D] fp32, mask[B,N] int32 (1 == masked out), W[D], b[D].
// out = mask ? b : (X - mean_n)/std_n * W + b   (std unbiased, ddof=1; REPLACE=0)
#define Bz 64
#define Nz 8192
#define Dz 128
#define D4 32          // D/4 float4 lanes
#define SPLITS 16      // stats blocks per batch
#define ROWS_PER_SPLIT (Nz / SPLITS)   // 512
#define RPB 256        // rows per block in normalize kernel

// Per-split partials: every slot is overwritten on every launch.
// -> no zero kernel, no atomics, deterministic under graph replay.
__device__ float g_psum[SPLITS][Bz * Dz];
__device__ float g_psq [SPLITS][Bz * Dz];
__device__ int   g_pcnt[SPLITS][Bz];

// grid (SPLITS, B), block 256.  Warp rg handles rows rg, rg+8, ... (64 rows).
// Unroll 4 with mask prefetch: 4 independent mask LDGs issue first, then up to
// 4 conditional float4 loads batch together -> MLP_p1 ~4.
__global__ void mn_stats_kernel(const float* __restrict__ X,
                                const int* __restrict__ mask) {
    const int b     = blockIdx.y;
    const int split = blockIdx.x;
    const int tid   = threadIdx.x;
    const int d4    = tid & 31;    // float4 lane in D
    const int rg    = tid >> 5;    // row group 0..7 (== warp id)
    const int row0  = split * ROWS_PER_SPLIT;

    const float4* Xb = (const float4*)(X + (size_t)b * Nz * Dz);
    const int*    mb = mask + (size_t)b * Nz;

    float4 s = make_float4(0.f, 0.f, 0.f, 0.f);
    float4 q = make_float4(0.f, 0.f, 0.f, 0.f);
    int cnt = 0;

    for (int r = row0 + rg; r < row0 + ROWS_PER_SPLIT; r += 32) {
        const int m0 = mb[r];
        const int m1 = mb[r + 8];
        const int m2 = mb[r + 16];
        const int m3 = mb[r + 24];
        if (!m0) {
            float4 v = Xb[(size_t)r * D4 + d4];
            s.x += v.x; s.y += v.y; s.z += v.z; s.w += v.w;
            q.x = fmaf(v.x, v.x, q.x); q.y = fmaf(v.y, v.y, q.y);
            q.z = fmaf(v.z, v.z, q.z); q.w = fmaf(v.w, v.w, q.w);
            cnt++;
        }
        if (!m1) {
            float4 v = Xb[(size_t)(r + 8) * D4 + d4];
            s.x += v.x; s.y += v.y; s.z += v.z; s.w += v.w;
            q.x = fmaf(v.x, v.x, q.x); q.y = fmaf(v.y, v.y, q.y);
            q.z = fmaf(v.z, v.z, q.z); q.w = fmaf(v.w, v.w, q.w);
            cnt++;
        }
        if (!m2) {
            float4 v = Xb[(size_t)(r + 16) * D4 + d4];
            s.x += v.x; s.y += v.y; s.z += v.z; s.w += v.w;
            q.x = fmaf(v.x, v.x, q.x); q.y = fmaf(v.y, v.y, q.y);
            q.z = fmaf(v.z, v.z, q.z); q.w = fmaf(v.w, v.w, q.w);
            cnt++;
        }
        if (!m3) {
            float4 v = Xb[(size_t)(r + 24) * D4 + d4];
            s.x += v.x; s.y += v.y; s.z += v.z; s.w += v.w;
            q.x = fmaf(v.x, v.x, q.x); q.y = fmaf(v.y, v.y, q.y);
            q.z = fmaf(v.z, v.z, q.z); q.w = fmaf(v.w, v.w, q.w);
            cnt++;
        }
    }

    __shared__ float ssum[8][Dz];
    __shared__ float ssq[8][Dz];
    __shared__ int   scnt[8];
    ((float4*)&ssum[rg][0])[d4] = s;
    ((float4*)&ssq[rg][0])[d4]  = q;
    if (d4 == 0) scnt[rg] = cnt;
    __syncthreads();

    if (tid < Dz) {
        float ts = 0.f, tq = 0.f;
        #pragma unroll
        for (int i = 0; i < 8; i++) { ts += ssum[i][tid]; tq += ssq[i][tid]; }
        g_psum[split][b * Dz + tid] = ts;      // plain store, overwritten every launch
        g_psq [split][b * Dz + tid] = tq;
    }
    if (tid == 0) {
        int c = 0;
        #pragma unroll
        for (int i = 0; i < 8; i++) c += scnt[i];
        g_pcnt[split][b] = c;
    }
}

// grid (N/RPB, B), block 256.  PDL launch; prologue overlaps stats tail.
// LIFO batch traversal; .cs loads/stores; masks staged in smem.
// Mainloop unroll 8: 8 independent redirect-loads batch per iteration
// (per-warp MLP ~8; regs ~64-72 -> 4 blocks/SM, no launch_bounds cap).
__global__ void mn_norm_kernel(const float* __restrict__ X,
                               const int* __restrict__ mask,
                               const float* __restrict__ W,
                               const float* __restrict__ bias,
                               float* __restrict__ out) {
    const int b   = Bz - 1 - blockIdx.y;    // reverse: most-recently-warmed first
    const int tid = threadIdx.x;

    __shared__ float sa[Dz];   // W * invstd
    __shared__ float sc[Dz];   // bias - mean * W * invstd
    __shared__ float sr[Dz];   // replacement value: 0*W + bias
    __shared__ int   smask[RPB];

    const int row0 = blockIdx.x * RPB;
    const int*  mb = mask + (size_t)b * Nz;

    // ---- stats-independent prologue (overlaps stats tail under PDL) ----
    smask[tid] = mb[row0 + tid];           // one coalesced 1KB burst
    float w = 0.f, bb = 0.f;
    if (tid < Dz) { w = W[tid]; bb = bias[tid]; }

    // ---- wait for stats grid completion (memory visible) ----
    cudaGridDependencySynchronize();

    if (tid < Dz) {
        float ts = 0.f, tq = 0.f;
        int   c  = 0;
        #pragma unroll
        for (int s = 0; s < SPLITS; s++) {
            ts += g_psum[s][b * Dz + tid];
            tq += g_psq [s][b * Dz + tid];
            c  += g_pcnt[s][b];
        }
        float fc   = (float)c;
        float mean = ts / fc;
        float var  = (tq - fc * mean * mean) / (fc - 1.0f);
        float inv  = rsqrtf(var);
        float a    = w * inv;
        sa[tid] = a;
        sc[tid] = bb - mean * a;
        sr[tid] = bb;
    }
    __syncthreads();

    const int d4 = tid & 31;
    const int rg = tid >> 5;
    const int dd = d4 * 4;

    const float4* Xb = (const float4*)(X + (size_t)b * Nz * Dz);
    float4*       Ob = (float4*)(out + (size_t)b * Nz * Dz);

    const float a0 = sa[dd], a1 = sa[dd + 1], a2 = sa[dd + 2], a3 = sa[dd + 3];
    const float c0 = sc[dd], c1 = sc[dd + 1], c2 = sc[dd + 2], c3 = sc[dd + 3];
    float4 rv;
    rv.x = sr[dd]; rv.y = sr[dd + 1]; rv.z = sr[dd + 2]; rv.w = sr[dd + 3];

    // 32 rows per warp, unroll 8 (4 iterations).  All loads unconditional
    // (masked rows redirected to L2-hot batch row 0); FSEL output select.
    for (int rr = rg; rr < RPB; rr += 64) {
        int   m[8];
        size_t idx[8];
        float4 v[8];

        #pragma unroll
        for (int k = 0; k < 8; k++) {
            const int r = rr + 8 * k;
            m[k]   = smask[r];
            idx[k] = m[k] ? (size_t)d4 : (size_t)(row0 + r) * D4 + d4;
        }
        #pragma unroll
        for (int k = 0; k < 8; k++) {
            v[k] = __ldcs(&Xb[idx[k]]);
        }
        #pragma unroll
        for (int k = 0; k < 8; k++) {
            float4 o;
            o.x = m[k] ? rv.x : fmaf(v[k].x, a0, c0);
            o.y = m[k] ? rv.y : fmaf(v[k].y, a1, c1);
            o.z = m[k] ? rv.z : fmaf(v[k].z, a2, c2);
            o.w = m[k] ? rv.w : fmaf(v[k].w, a3, c3);
            __stcs(&Ob[(size_t)(row0 + rr + 8 * k) * D4 + d4], o);
        }
    }
}

extern "C" void kernel_launch(void* const* d_in, const int* in_sizes, int n_in,
                              void* d_out, int out_size) {
    const float* X    = (const float*)d_in[0];
    const int*   mask = (const int*)d_in[1];
    const float* W    = (const float*)d_in[2];
    const float* bias = (const float*)d_in[3];
    float* out        = (float*)d_out;

    dim3 g1(SPLITS, Bz);
    mn_stats_kernel<<<g1, 256>>>(X, mask);

    // PDL launch: norm blocks dispatch while stats drains; the in-kernel
    // cudaGridDependencySynchronize() enforces the data dependency.
    dim3 g2(Nz / RPB, Bz);
    cudaLaunchConfig_t cfg = {};
    cfg.gridDim  = g2;
    cfg.blockDim = dim3(256, 1, 1);
    cfg.stream   = 0;
    cudaLaunchAttribute attrs[1];
    attrs[0].id = cudaLaunchAttributeProgrammaticStreamSerialization;
    attrs[0].val.programmaticStreamSerializationAllowed = 1;
    cfg.attrs    = attrs;
    cfg.numAttrs = 1;
    cudaLaunchKernelEx(&cfg, mn_norm_kernel, X, mask, W, bias, out);
}